// round 8
// baseline (speedup 1.0000x reference)
#include <cuda_runtime.h>
#include <cstdint>
#include <cstddef>

// Problem constants
#define BATCH 16384
#define F 512
#define CLUSTER 16       // one 16-CTA cluster (non-portable size), 1 GPC
#define TPB 512          // 16 warps; warp w owns columns b*32+2w, +1

// Scratch (device globals: no allocation allowed in kernel_launch)
__device__ __align__(16) float g_xwz[(size_t)BATCH * F];   // x@Wz + bz
__device__ __align__(16) float g_xwh[(size_t)BATCH * F];   // x@Wh + bh
__device__ float g_sink;                                   // never actually written

// ---------------------------------------------------------------------------
// PTX helpers (all instruction forms proven in the R6 run)
// ---------------------------------------------------------------------------
__device__ __forceinline__ uint32_t smem_u32(const void* p) {
    uint32_t a;
    asm("{ .reg .u64 t; cvta.to.shared.u64 t, %1; cvt.u32.u64 %0, t; }"
        : "=r"(a) : "l"(p));
    return a;
}
__device__ __forceinline__ unsigned long long fma2(
    unsigned long long a, unsigned long long b, unsigned long long c) {
    unsigned long long d;
    asm("fma.rn.f32x2 %0, %1, %2, %3;" : "=l"(d) : "l"(a), "l"(b), "l"(c));
    return d;
}
__device__ __forceinline__ unsigned long long add2(
    unsigned long long a, unsigned long long b) {
    unsigned long long d;
    asm("add.rn.f32x2 %0, %1, %2;" : "=l"(d) : "l"(a), "l"(b));
    return d;
}
__device__ __forceinline__ float pair_sum(unsigned long long p) {
    uint32_t lo, hi;
    asm("mov.b64 {%0, %1}, %2;" : "=r"(lo), "=r"(hi) : "l"(p));
    return __uint_as_float(lo) + __uint_as_float(hi);
}
__device__ __forceinline__ unsigned long long pack2(float a0, float a1) {
    unsigned long long p;
    asm("mov.b64 %0, {%1, %2};" : "=l"(p)
        : "r"(__float_as_uint(a0)), "r"(__float_as_uint(a1)));
    return p;
}
__device__ __forceinline__ uint32_t mapa_rank(uint32_t laddr, int rank) {
    uint32_t r;
    asm("mapa.shared::cluster.u32 %0, %1, %2;" : "=r"(r) : "r"(laddr), "r"(rank));
    return r;
}
__device__ __forceinline__ void dsmem_store_f32(uint32_t raddr, float v) {
    asm volatile("st.shared::cluster.f32 [%0], %1;"
                 :: "r"(raddr), "f"(v) : "memory");
}
__device__ __forceinline__ void mbar_init(uint32_t addr, uint32_t cnt) {
    asm volatile("mbarrier.init.shared.b64 [%0], %1;"
                 :: "r"(addr), "r"(cnt) : "memory");
}
__device__ __forceinline__ void mbar_arrive_remote(uint32_t raddr) {
    asm volatile("mbarrier.arrive.shared::cluster.b64 _, [%0];"
                 :: "r"(raddr) : "memory");
}
// Non-blocking phase test: try_wait with immediate suspend-time hint 0.
// Returns 1 if the phase completed. (try_wait form proven in R6.)
__device__ __forceinline__ uint32_t mbar_poll(uint32_t addr, uint32_t parity) {
    uint32_t done;
    asm volatile(
        "{\n\t"
        ".reg .pred P;\n\t"
        "mbarrier.try_wait.parity.shared::cta.b64 P, [%1], %2, 0;\n\t"
        "selp.b32 %0, 1, 0, P;\n\t"
        "}"
        : "=r"(done) : "r"(addr), "r"(parity) : "memory");
    return done;
}
__device__ __forceinline__ void fence_release_cluster() {
    asm volatile("fence.release.cluster;" ::: "memory");
}
__device__ __forceinline__ void fence_acquire_cluster() {
    asm volatile("fence.acquire.cluster;" ::: "memory");
}
__device__ __forceinline__ void cluster_arrive() {
    asm volatile("barrier.cluster.arrive.aligned;" ::: "memory");
}
__device__ __forceinline__ void cluster_wait() {
    asm volatile("barrier.cluster.wait.aligned;" ::: "memory");
}

// ---------------------------------------------------------------------------
// Phase 1: batched GEMM  C = A(16384x512) * W(512x512) + bias
// ---------------------------------------------------------------------------
#define BM 64
#define BN 64
#define BKK 16

__global__ void __launch_bounds__(256) gemm_kernel(
    const float* __restrict__ A,
    const float* __restrict__ Wz, const float* __restrict__ bz,
    const float* __restrict__ Wh, const float* __restrict__ bh)
{
    const float* B    = (blockIdx.z == 0) ? Wz : Wh;
    const float* bias = (blockIdx.z == 0) ? bz : bh;
    float*       C    = (blockIdx.z == 0) ? g_xwz : g_xwh;

    __shared__ float As[BKK][BM];
    __shared__ float Bs[BKK][BN];

    const int row0 = blockIdx.y * BM;
    const int col0 = blockIdx.x * BN;
    const int tid  = threadIdx.x;

    const int a_m = tid >> 2;
    const int a_k = (tid & 3) * 4;
    const int b_k = tid >> 4;
    const int b_n = (tid & 15) * 4;

    const int ty = tid >> 4;
    const int tx = tid & 15;

    float acc[4][4] = {};

    for (int k0 = 0; k0 < F; k0 += BKK) {
        float4 av = *(const float4*)(A + (size_t)(row0 + a_m) * F + k0 + a_k);
        As[a_k + 0][a_m] = av.x;
        As[a_k + 1][a_m] = av.y;
        As[a_k + 2][a_m] = av.z;
        As[a_k + 3][a_m] = av.w;
        float4 bv = *(const float4*)(B + (size_t)(k0 + b_k) * F + col0 + b_n);
        *(float4*)&Bs[b_k][b_n] = bv;
        __syncthreads();
#pragma unroll
        for (int k = 0; k < BKK; k++) {
            float ar[4], br[4];
            *(float4*)ar = *(const float4*)&As[k][ty * 4];
            *(float4*)br = *(const float4*)&Bs[k][tx * 4];
#pragma unroll
            for (int i = 0; i < 4; i++)
#pragma unroll
                for (int jj = 0; jj < 4; jj++)
                    acc[i][jj] = fmaf(ar[i], br[jj], acc[i][jj]);
        }
        __syncthreads();
    }

    float4 bv;
    bv.x = __ldg(&bias[col0 + tx * 4 + 0]);
    bv.y = __ldg(&bias[col0 + tx * 4 + 1]);
    bv.z = __ldg(&bias[col0 + tx * 4 + 2]);
    bv.w = __ldg(&bias[col0 + tx * 4 + 3]);
#pragma unroll
    for (int i = 0; i < 4; i++) {
        float4 o;
        o.x = acc[i][0] + bv.x;
        o.y = acc[i][1] + bv.y;
        o.z = acc[i][2] + bv.z;
        o.w = acc[i][3] + bv.w;
        *(float4*)(C + (size_t)(row0 + ty * 4 + i) * F + col0 + tx * 4) = o;
    }
}

// ---------------------------------------------------------------------------
// Phase 2: scan. R6 protocol EXACTLY (lane-scatter DSMEM + per-CTA mbarriers,
// fence.release.cluster + remote arrive, fence.acquire.cluster after wait).
// Single change vs R6: the wait is a BUSY poll (try_wait with 0 suspend hint
// in a loop, FMA filler between polls, all 512 threads) instead of a HW-sleep
// wait — the anti-DVFS experiment.
//
// Runahead bound (2 mbarriers, slot t&1, parity (t>>1)&1): to arrive for
// step t+2 a CTA passed its wait for t+1, which required ALL CTAs' arrivals
// for t+1, each requiring that CTA to pass its wait for t -> the mb[t&1]
// phase for step t completed cluster-wide before any t+2 arrival. Same
// argument proves sbuf[t&1] overwrite safety. Gang-scheduled: no deadlock.
// ---------------------------------------------------------------------------
__global__ void __launch_bounds__(TPB, 1) scan_kernel(
    const float* __restrict__ Uz,
    const float* __restrict__ Uh,
    float* __restrict__ out)
{
    __shared__ float sbuf[2][F];
    __shared__ __align__(8) unsigned long long mb[2];

    const int b = blockIdx.x;              // cluster rank
    const int w = threadIdx.x >> 5;
    const int l = threadIdx.x & 31;
    const int hw = l >> 4;
    const int hl = l & 15;                 // target rank for lane scatter
    const int mycol = b * 32 + w * 2 + hw;
    const int rbase = hl * 32;
    const bool head = (hl == 0);

    if (threadIdx.x == 0) {
        mbar_init(smem_u32(&mb[0]), CLUSTER);
        mbar_init(smem_u32(&mb[1]), CLUSTER);
    }
    __syncthreads();
    cluster_arrive();          // one-time: all inits visible before any arrive

    // Preload packed U slices (64 regs)
    unsigned long long uzp[16], uhp[16];
#pragma unroll
    for (int i = 0; i < 16; i++) {
        uzp[i] = pack2(Uz[(size_t)(rbase + 2 * i) * F + mycol],
                       Uz[(size_t)(rbase + 2 * i + 1) * F + mycol]);
        uhp[i] = pack2(Uh[(size_t)(rbase + 2 * i) * F + mycol],
                       Uh[(size_t)(rbase + 2 * i + 1) * F + mycol]);
    }

    const uint32_t dst0 = mapa_rank(smem_u32(&sbuf[0][mycol]), hl);
    const uint32_t dst1 = mapa_rank(smem_u32(&sbuf[1][mycol]), hl);
    const uint32_t mb0_l = smem_u32(&mb[0]);
    const uint32_t mb1_l = smem_u32(&mb[1]);
    const uint32_t mb0_r = mapa_rank(mb0_l, w);   // arrive target for warp w
    const uint32_t mb1_r = mapa_rank(mb1_l, w);

    cluster_wait();

    // Anti-DVFS filler accumulator (value is numerically inert)
    float fill = (float)(threadIdx.x + 1) * 1.0e-18f;

    // ---- t = 0: m_prev = 0 ----
    {
        float mn = 0.f;
        if (head) {
            float xz = __ldg(&g_xwz[mycol]);
            float xh = __ldg(&g_xwh[mycol]);
            float z = __fdividef(1.f, 1.f + __expf(-xz));
            float h = 1.f - __fdividef(2.f, __expf(2.f * xh) + 1.f);
            mn = z * h;
            out[mycol] = mn;
        }
        mn = __shfl_sync(0xffffffffu, mn, l & 16);
        dsmem_store_f32(dst0, mn);
        __syncthreads();
        if (l == 0) {
            fence_release_cluster();
            mbar_arrive_remote(mb0_r);
        }
    }
    // Prefetch x@W for t = 1
    float xz_p = 0.f, xh_p = 0.f;
    if (head) {
        xz_p = __ldg(&g_xwz[F + mycol]);
        xh_p = __ldg(&g_xwh[F + mycol]);
    }

    for (int t = 1; t < BATCH; t++) {
        const int sp = (t - 1) & 1;                 // slot holding m_{t-1}
        const uint32_t wmb = sp ? mb1_l : mb0_l;
        const uint32_t par = (unsigned)((t - 1) >> 1) & 1u;

        // BUSY wait: non-blocking try_wait poll + FMA filler (keeps clocks up)
        while (!mbar_poll(wmb, par)) {
#pragma unroll
            for (int i = 0; i < 8; i++)
                fill = fmaf(fill, 1.0000001f, 1.0e-30f);
        }
        fence_acquire_cluster();

        // Gate scalar m_{t-1}[mycol] (local LDS)
        float mj = 0.f;
        if (head) mj = sbuf[sp][mycol];

        // 32 state rows as 16 packed f32x2 from local smem
        const unsigned long long* mp =
            (const unsigned long long*)&sbuf[sp][rbase];

        unsigned long long az0 = 0ull, az1 = 0ull, ah0 = 0ull, ah1 = 0ull;
#pragma unroll
        for (int i = 0; i < 16; i += 2) {
            unsigned long long m0 = mp[i], m1 = mp[i + 1];
            az0 = fma2(m0, uzp[i], az0);
            az1 = fma2(m1, uzp[i + 1], az1);
            ah0 = fma2(m0, uhp[i], ah0);
            ah1 = fma2(m1, uhp[i + 1], ah1);
        }
        float az = pair_sum(add2(az0, az1));
        float ah = pair_sum(add2(ah0, ah1));

        // 4-level butterfly inside the half-warp
#pragma unroll
        for (int s = 8; s > 0; s >>= 1) {
            az += __shfl_xor_sync(0xffffffffu, az, s);
            ah += __shfl_xor_sync(0xffffffffu, ah, s);
        }

        float mn = 0.f;
        if (head) {
            float zp = az + xz_p;
            float hp = ah + xh_p;
            float z = __fdividef(1.f, 1.f + __expf(-zp));            // sigmoid
            float h = 1.f - __fdividef(2.f, __expf(2.f * hp) + 1.f); // tanh
            mn = fmaf(z, h - mj, mj);
            out[(size_t)t * F + mycol] = mn;
        }
        mn = __shfl_sync(0xffffffffu, mn, l & 16);

        if (t < BATCH - 1) {                        // last step publishes nothing
            dsmem_store_f32((t & 1) ? dst1 : dst0, mn);
            __syncthreads();
            if (l == 0) {
                fence_release_cluster();
                mbar_arrive_remote((t & 1) ? mb1_r : mb0_r);
            }
        }

        // Prefetch x@W for t+1 (covered by next step's wait window)
        if (head && t + 1 < BATCH) {
            xz_p = __ldg(&g_xwz[(size_t)(t + 1) * F + mycol]);
            xh_p = __ldg(&g_xwh[(size_t)(t + 1) * F + mycol]);
        }
    }

    // Keep the filler live; the key can never match so g_sink is never written.
    if (__float_as_uint(fill) == 0xdeadbeefu) g_sink = fill;

    cluster_arrive();
    cluster_wait();
}

// ---------------------------------------------------------------------------
// Launch: GEMMs -> single-cluster scan. All graph-capturable.
// ---------------------------------------------------------------------------
extern "C" void kernel_launch(void* const* d_in, const int* in_sizes, int n_in,
                              void* d_out, int out_size)
{
    const float* x  = (const float*)d_in[0];
    const float* Wz = (const float*)d_in[1];
    const float* Uz = (const float*)d_in[2];
    const float* bz = (const float*)d_in[3];
    const float* Wh = (const float*)d_in[4];
    const float* Uh = (const float*)d_in[5];
    const float* bh = (const float*)d_in[6];
    float* out = (float*)d_out;

    dim3 ggrid(F / BN, BATCH / BM, 2);   // 8 x 256 x 2
    gemm_kernel<<<ggrid, 256>>>(x, Wz, bz, Wh, bh);

    cudaFuncSetAttribute(scan_kernel,
                         cudaFuncAttributeNonPortableClusterSizeAllowed, 1);
    cudaLaunchConfig_t cfg = {};
    cfg.gridDim  = dim3(CLUSTER, 1, 1);
    cfg.blockDim = dim3(TPB, 1, 1);
    cfg.dynamicSmemBytes = 0;
    cfg.stream = 0;
    cudaLaunchAttribute attrs[1];
    attrs[0].id = cudaLaunchAttributeClusterDimension;
    attrs[0].val.clusterDim.x = CLUSTER;
    attrs[0].val.clusterDim.y = 1;
    attrs[0].val.clusterDim.z = 1;
    cfg.attrs = attrs;
    cfg.numAttrs = 1;
    cudaLaunchKernelEx(&cfg, scan_kernel, Uz, Uh, out);
}

// round 9
// speedup vs baseline: 2.2713x; 2.2713x over previous
#include <cuda_runtime.h>
#include <cstdint>
#include <cstddef>

// Problem constants
#define BATCH 16384
#define F 512
#define CLUSTER 16       // one 16-CTA cluster (non-portable size), 1 GPC
#define TPB 512          // 16 warps; warp w owns columns b*32+2w, +1
#define SLOTS 4          // state slot ring (proof below shows 2 suffice)

// Scratch (device globals: no allocation allowed in kernel_launch)
__device__ __align__(16) float g_xwz[(size_t)BATCH * F];   // x@Wz + bz
__device__ __align__(16) float g_xwh[(size_t)BATCH * F];   // x@Wh + bh

// ---------------------------------------------------------------------------
// PTX helpers
// ---------------------------------------------------------------------------
__device__ __forceinline__ uint32_t smem_u32(const void* p) {
    uint32_t a;
    asm("{ .reg .u64 t; cvta.to.shared.u64 t, %1; cvt.u32.u64 %0, t; }"
        : "=r"(a) : "l"(p));
    return a;
}
__device__ __forceinline__ unsigned long long fma2(
    unsigned long long a, unsigned long long b, unsigned long long c) {
    unsigned long long d;
    asm("fma.rn.f32x2 %0, %1, %2, %3;" : "=l"(d) : "l"(a), "l"(b), "l"(c));
    return d;
}
__device__ __forceinline__ unsigned long long add2(
    unsigned long long a, unsigned long long b) {
    unsigned long long d;
    asm("add.rn.f32x2 %0, %1, %2;" : "=l"(d) : "l"(a), "l"(b));
    return d;
}
__device__ __forceinline__ float pair_sum(unsigned long long p) {
    uint32_t lo, hi;
    asm("mov.b64 {%0, %1}, %2;" : "=r"(lo), "=r"(hi) : "l"(p));
    return __uint_as_float(lo) + __uint_as_float(hi);
}
__device__ __forceinline__ unsigned long long pack2(float a0, float a1) {
    unsigned long long p;
    asm("mov.b64 %0, {%1, %2};" : "=l"(p)
        : "r"(__float_as_uint(a0)), "r"(__float_as_uint(a1)));
    return p;
}
__device__ __forceinline__ uint32_t mapa_rank(uint32_t laddr, int rank) {
    uint32_t r;
    asm("mapa.shared::cluster.u32 %0, %1, %2;" : "=r"(r) : "r"(laddr), "r"(rank));
    return r;
}
__device__ __forceinline__ void dsmem_store_f32(uint32_t raddr, float v) {
    asm volatile("st.shared::cluster.f32 [%0], %1;"
                 :: "r"(raddr), "f"(v) : "memory");
}
// Release STORE to a remote flag: orders everything happens-before it (incl.
// other threads' DSMEM stores joined via __syncthreads) ahead of the flag.
__device__ __forceinline__ void st_release_flag(uint32_t raddr, unsigned v) {
    asm volatile("st.release.cluster.shared::cluster.u32 [%0], %1;"
                 :: "r"(raddr), "r"(v) : "memory");
}
// Acquire LOAD of a local flag word (written remotely): pairs with the
// release store; on observing it, the producer's data stores are visible.
__device__ __forceinline__ unsigned ld_acquire_flag(uint32_t laddr) {
    unsigned v;
    asm volatile("ld.acquire.cluster.shared::cta.u32 %0, [%1];"
                 : "=r"(v) : "r"(laddr) : "memory");
    return v;
}
__device__ __forceinline__ void lds_v2_u64(uint32_t addr,
                                           unsigned long long& a,
                                           unsigned long long& b) {
    asm volatile("ld.shared.v2.u64 {%0, %1}, [%2];"
                 : "=l"(a), "=l"(b) : "r"(addr));
}
__device__ __forceinline__ void cluster_arrive() {
    asm volatile("barrier.cluster.arrive.aligned;" ::: "memory");
}
__device__ __forceinline__ void cluster_wait() {
    asm volatile("barrier.cluster.wait.aligned;" ::: "memory");
}

// ---------------------------------------------------------------------------
// Phase 1: batched GEMM  C = A(16384x512) * W(512x512) + bias
// ---------------------------------------------------------------------------
#define BM 64
#define BN 64
#define BKK 16

__global__ void __launch_bounds__(256) gemm_kernel(
    const float* __restrict__ A,
    const float* __restrict__ Wz, const float* __restrict__ bz,
    const float* __restrict__ Wh, const float* __restrict__ bh)
{
    const float* B    = (blockIdx.z == 0) ? Wz : Wh;
    const float* bias = (blockIdx.z == 0) ? bz : bh;
    float*       C    = (blockIdx.z == 0) ? g_xwz : g_xwh;

    __shared__ float As[BKK][BM];
    __shared__ float Bs[BKK][BN];

    const int row0 = blockIdx.y * BM;
    const int col0 = blockIdx.x * BN;
    const int tid  = threadIdx.x;

    const int a_m = tid >> 2;
    const int a_k = (tid & 3) * 4;
    const int b_k = tid >> 4;
    const int b_n = (tid & 15) * 4;

    const int ty = tid >> 4;
    const int tx = tid & 15;

    float acc[4][4] = {};

    for (int k0 = 0; k0 < F; k0 += BKK) {
        float4 av = *(const float4*)(A + (size_t)(row0 + a_m) * F + k0 + a_k);
        As[a_k + 0][a_m] = av.x;
        As[a_k + 1][a_m] = av.y;
        As[a_k + 2][a_m] = av.z;
        As[a_k + 3][a_m] = av.w;
        float4 bv = *(const float4*)(B + (size_t)(k0 + b_k) * F + col0 + b_n);
        *(float4*)&Bs[b_k][b_n] = bv;
        __syncthreads();
#pragma unroll
        for (int k = 0; k < BKK; k++) {
            float ar[4], br[4];
            *(float4*)ar = *(const float4*)&As[k][ty * 4];
            *(float4*)br = *(const float4*)&Bs[k][tx * 4];
#pragma unroll
            for (int i = 0; i < 4; i++)
#pragma unroll
                for (int jj = 0; jj < 4; jj++)
                    acc[i][jj] = fmaf(ar[i], br[jj], acc[i][jj]);
        }
        __syncthreads();
    }

    float4 bv;
    bv.x = __ldg(&bias[col0 + tx * 4 + 0]);
    bv.y = __ldg(&bias[col0 + tx * 4 + 1]);
    bv.z = __ldg(&bias[col0 + tx * 4 + 2]);
    bv.w = __ldg(&bias[col0 + tx * 4 + 3]);
#pragma unroll
    for (int i = 0; i < 4; i++) {
        float4 o;
        o.x = acc[i][0] + bv.x;
        o.y = acc[i][1] + bv.y;
        o.z = acc[i][2] + bv.z;
        o.w = acc[i][3] + bv.w;
        *(float4*)(C + (size_t)(row0 + ty * 4 + i) * F + col0 + tx * 4) = o;
    }
}

// ---------------------------------------------------------------------------
// Phase 2: scan, one 16-CTA cluster, fence-free release-flag protocol.
//
// Layout (as R8): CTA b owns columns b*32..+31; warp w owns cols 2w,2w+1;
// lane l: column j0+(l>>4), rows (l&15)*32..+31, register U (f32x2 packed).
//
// Per step t:
//  - every lane DSMEM-stores its column's m_t into ALL ranks (its lane-rank
//    hl) at sval[t&3][paddr(col)]  (weak st.shared::cluster, proven form)
//  - __syncthreads; warp 0 lanes 0..15 publish eflag = t+1 to rank=lane via
//    ONE st.release.cluster each (release orders the whole CTA's stores,
//    joined by the barrier). No fences, no mbarriers.
//  - consumer: each lane spins on ONE local word (its producer's flag; all
//    its 32 rows come from producer CTA hl) with ld.acquire.cluster; plus
//    the flag of CTA b for the gate scalar m[mycol].
//
// Bank swizzle: value for column c lives at element paddr(c): 16B-chunk index
// (c>>2) is XORed with (c>>5)&7 within its 8-chunk region. Consumer lane hl
// reading logical chunk j hits bank-group j^(hl&7): the 16 lanes spread over
// all 8 groups (deg 2 = the 256B/phase minimum). Producer and consumer use
// the same formula, so it is a pure relabeling.
//
// Slot-ring safety (SLOTS=4, need 2): observing flag_C >= t implies CTA C
// passed its step-(t-1) __syncthreads, i.e. ALL C's threads finished reading
// their step-(t-2) inputs. A writer stores step t only after observing all
// flags >= t, hence after every thread cluster-wide finished reading step
// t-2 <= step t-SLOTS's readers are long done. Gang-scheduled: no deadlock.
// ---------------------------------------------------------------------------
__global__ void __launch_bounds__(TPB, 1) scan_kernel(
    const float* __restrict__ Uz,
    const float* __restrict__ Uh,
    float* __restrict__ out)
{
    __shared__ float sval[SLOTS][F];
    __shared__ unsigned eflag[16 * 8];     // 16 flags, 32B apart

    const int b = blockIdx.x;              // cluster rank
    const int w = threadIdx.x >> 5;
    const int l = threadIdx.x & 31;
    const int hw = l >> 4;
    const int hl = l & 15;                 // producer rank for this lane's rows
    const int mycol = b * 32 + w * 2 + hw;
    const int rbase = hl * 32;
    const bool head = (hl == 0);           // one writer of out[] per column

    if (threadIdx.x < 16) eflag[threadIdx.x * 8] = 0u;
    __syncthreads();
    cluster_arrive();                      // flags everywhere init'd before use

    // Preload packed U slices (rows rbase+2i, rbase+2i+1 of column mycol)
    unsigned long long uzp[16], uhp[16];
#pragma unroll
    for (int i = 0; i < 16; i++) {
        uzp[i] = pack2(Uz[(size_t)(rbase + 2 * i) * F + mycol],
                       Uz[(size_t)(rbase + 2 * i + 1) * F + mycol]);
        uhp[i] = pack2(Uh[(size_t)(rbase + 2 * i) * F + mycol],
                       Uh[(size_t)(rbase + 2 * i + 1) * F + mycol]);
    }

    // Swizzled element index for column c (see header comment)
    const int pchunk = ((mycol >> 5) << 3) | (((mycol >> 2) & 7) ^ ((mycol >> 5) & 7));
    const int poff = (pchunk << 2) | (mycol & 3);      // element index in sval row

    uint32_t dstv[SLOTS];
#pragma unroll
    for (int s = 0; s < SLOTS; s++)
        dstv[s] = mapa_rank(smem_u32(&sval[s][0]) + poff * 4, hl);
    uint32_t rflag = 0;
    if (w == 0 && l < 16)
        rflag = mapa_rank(smem_u32(&eflag[b * 8]), l);
    const uint32_t fl_own = smem_u32(&eflag[hl * 8]);  // my rows' producer
    const uint32_t fl_b   = smem_u32(&eflag[b * 8]);   // gate scalar's producer
    const int sw = hl & 7;                             // consumer swizzle key

    cluster_wait();

    // x@W terms for t = 0 in all lanes (same addr per half-warp -> broadcast)
    float xz_p = __ldg(&g_xwz[mycol]);
    float xh_p = __ldg(&g_xwh[mycol]);
    float fill = (float)(threadIdx.x + 1) * 1.0e-18f;  // spin filler

    for (int t = 0; t < BATCH; t++) {
        unsigned long long az0 = 0ull, az1 = 0ull, ah0 = 0ull, ah1 = 0ull;
        float mj = 0.f;

        if (t > 0) {
            // Spin until producers hl and b have published step t-1.
            for (;;) {
                unsigned e1 = ld_acquire_flag(fl_own);
                unsigned e2 = ld_acquire_flag(fl_b);
                if ((int)e1 >= t && (int)e2 >= t) break;
                fill = fmaf(fill, 1.0000001f, 1.0e-30f);
            }
            const uint32_t slotbase = smem_u32(&sval[(t - 1) & (SLOTS - 1)][0]);
            mj = *(const float*)((const char*)sval + ((t - 1) & (SLOTS - 1)) * F * 4
                                 + poff * 4);
            // Fused swizzled loads + FMAs (2 u64 live at a time)
#pragma unroll
            for (int j = 0; j < 8; j++) {
                uint32_t addr = slotbase + (((hl << 3) | (j ^ sw)) << 4);
                unsigned long long m0, m1;
                lds_v2_u64(addr, m0, m1);
                az0 = fma2(m0, uzp[2 * j], az0);
                az1 = fma2(m1, uzp[2 * j + 1], az1);
                ah0 = fma2(m0, uhp[2 * j], ah0);
                ah1 = fma2(m1, uhp[2 * j + 1], ah1);
            }
        }

        float az = pair_sum(add2(az0, az1));
        float ah = pair_sum(add2(ah0, ah1));
        // 4-level butterfly inside the half-warp: sum lands in every lane
#pragma unroll
        for (int s = 8; s > 0; s >>= 1) {
            az += __shfl_xor_sync(0xffffffffu, az, s);
            ah += __shfl_xor_sync(0xffffffffu, ah, s);
        }

        // All lanes compute the gate (warp-instruction count identical to
        // head-only; removes the broadcast shfl from the critical path).
        float zp = az + xz_p;
        float hp = ah + xh_p;
        float z = __fdividef(1.f, 1.f + __expf(-zp));            // sigmoid
        float h = 1.f - __fdividef(2.f, __expf(2.f * hp) + 1.f); // tanh
        float mn = fmaf(z, h - mj, mj);

        if (head) out[(size_t)t * F + mycol] = mn;

        if (t < BATCH - 1) {
            dsmem_store_f32(dstv[t & (SLOTS - 1)], mn);
            __syncthreads();
            if (w == 0 && l < 16)
                st_release_flag(rflag, (unsigned)(t + 1));
            // Prefetch x@W for t+1 (overlaps peers' skew + next spin)
            xz_p = __ldg(&g_xwz[(size_t)(t + 1) * F + mycol]);
            xh_p = __ldg(&g_xwh[(size_t)(t + 1) * F + mycol]);
        }
    }

    // Keep the filler live; condition can never hold.
    if (__float_as_uint(fill) == 0xdeadbeefu) out[0] = fill;

    cluster_arrive();
    cluster_wait();
}

// ---------------------------------------------------------------------------
// Launch: GEMMs -> single-cluster scan. All graph-capturable.
// ---------------------------------------------------------------------------
extern "C" void kernel_launch(void* const* d_in, const int* in_sizes, int n_in,
                              void* d_out, int out_size)
{
    const float* x  = (const float*)d_in[0];
    const float* Wz = (const float*)d_in[1];
    const float* Uz = (const float*)d_in[2];
    const float* bz = (const float*)d_in[3];
    const float* Wh = (const float*)d_in[4];
    const float* Uh = (const float*)d_in[5];
    const float* bh = (const float*)d_in[6];
    float* out = (float*)d_out;

    dim3 ggrid(F / BN, BATCH / BM, 2);   // 8 x 256 x 2
    gemm_kernel<<<ggrid, 256>>>(x, Wz, bz, Wh, bh);

    cudaFuncSetAttribute(scan_kernel,
                         cudaFuncAttributeNonPortableClusterSizeAllowed, 1);
    cudaLaunchConfig_t cfg = {};
    cfg.gridDim  = dim3(CLUSTER, 1, 1);
    cfg.blockDim = dim3(TPB, 1, 1);
    cfg.dynamicSmemBytes = 0;
    cfg.stream = 0;
    cudaLaunchAttribute attrs[1];
    attrs[0].id = cudaLaunchAttributeClusterDimension;
    attrs[0].val.clusterDim.x = CLUSTER;
    attrs[0].val.clusterDim.y = 1;
    attrs[0].val.clusterDim.z = 1;
    cfg.attrs = attrs;
    cfg.numAttrs = 1;
    cudaLaunchKernelEx(&cfg, scan_kernel, Uz, Uh, out);
}